// round 1
// baseline (speedup 1.0000x reference)
#include <cuda_runtime.h>
#include <math.h>

#define HD 450
#define NTREE 32
#define NB 1024
#define NNODE (NB*NTREE)

// ---------------- scratch (static device memory; no allocations) ----------------
__device__ float g_xz[NNODE*HD];   // x@Wz_top + bz  (per node)
__device__ float g_xh[NNODE*HD];   // x@Wh_top + bh
__device__ float g_xr[NNODE*HD];   // x@Wr + bU
__device__ float g_m [NNODE*HD];   // message per upward edge, indexed by child node
__device__ float g_rm[NNODE*HD];   // r*m per upward edge
__device__ float g_s [NB*16*HD];   // level scratch (max 16 active nodes/tree)
__device__ float g_av[NB*16*HD];
__device__ float g_zp[NB*16*HD];
__device__ float g_hp[NB*16*HD];
__device__ float g_rp[NB*16*HD];

constexpr int GBM = 128;
constexpr int GBN = 64;
constexpr int GBK = 16;

// ---------------- generic tiled SGEMM, N fixed = 450 ----------------
// C[M x 450] = Arows[M x K] @ W[K x 450] (+bias) with pluggable A-row source:
//  AMODE 0: dense A (stride 450)
//  AMODE 1: A = g_m with node map: row a -> node (a/cnt)*32 + lo + a%cnt
//  AMODE 2: A = emb[wid[row]]  (precompute gather)
//  AMODE 3: final: row = tree t; k<450 -> emb[wid[t*32]][k]; else m[t,1]+m[t,2]
//  EPI 0: plain store; EPI 1: +bias; EPI 2: relu(acc+bias) (final output)
template<int AMODE, int EPI>
__global__ __launch_bounds__(256) void gemm_k(
    const float* __restrict__ A, const float* __restrict__ W,
    const float* __restrict__ bias, float* __restrict__ C,
    int M, int K, int lo, int cnt,
    const int* __restrict__ wid, const float* __restrict__ emb,
    const float* __restrict__ maux)
{
    __shared__ float As[GBM][GBK];
    __shared__ float Bs[GBK][GBN];

    const int tid = threadIdx.x;
    const int m0 = blockIdx.y * GBM;
    const int n0 = blockIdx.x * GBN;
    const int tx = tid & 15;
    const int ty = tid >> 4;

    float acc[8][4];
#pragma unroll
    for (int i = 0; i < 8; i++)
#pragma unroll
        for (int j = 0; j < 4; j++) acc[i][j] = 0.f;

    for (int k0 = 0; k0 < K; k0 += GBK) {
        // ---- load A tile (128 x 16) as float2, coalesced ----
#pragma unroll
        for (int i = 0; i < 4; i++) {
            int lin = tid + i * 256;           // 0..1023 (float2 index)
            int row = lin >> 3;                // 0..127
            int k2  = lin & 7;
            int k   = k0 + k2 * 2;             // even
            int arow = m0 + row;
            float2 v = make_float2(0.f, 0.f);
            if (arow < M) {
                if constexpr (AMODE == 0) {
                    if (k + 1 < K)      v = *(const float2*)&A[arow * HD + k];
                    else if (k < K)     v.x = A[arow * HD + k];
                } else if constexpr (AMODE == 1) {
                    int tt = arow / cnt;
                    int node = tt * NTREE + lo + (arow - tt * cnt);
                    if (k + 1 < K)      v = *(const float2*)&A[node * HD + k];
                    else if (k < K)     v.x = A[node * HD + k];
                } else if constexpr (AMODE == 2) {
                    int w = wid[arow];
                    if (k + 1 < K)      v = *(const float2*)&emb[w * HD + k];
                    else if (k < K)     v.x = emb[w * HD + k];
                } else { // AMODE == 3
                    if (k < HD) {
                        v = *(const float2*)&emb[wid[arow * NTREE] * HD + k];
                    } else if (k < K) {
                        int kk = k - HD;
                        float2 u1 = *(const float2*)&maux[(arow * NTREE + 1) * HD + kk];
                        float2 u2 = *(const float2*)&maux[(arow * NTREE + 2) * HD + kk];
                        v = make_float2(u1.x + u2.x, u1.y + u2.y);
                    }
                }
            }
            *(float2*)&As[row][k2 * 2] = v;
        }
        // ---- load B tile (16 x 64) ----
#pragma unroll
        for (int i = 0; i < 4; i++) {
            int lin = tid + i * 256;     // 0..1023
            int kk  = lin >> 6;          // 0..15
            int col = lin & 63;
            int k   = k0 + kk;
            int j   = n0 + col;
            Bs[kk][col] = (k < K && j < HD) ? W[k * HD + j] : 0.f;
        }
        __syncthreads();

#pragma unroll
        for (int kk = 0; kk < GBK; kk++) {
            float4 b = *(const float4*)&Bs[kk][tx * 4];
#pragma unroll
            for (int ii = 0; ii < 8; ii++) {
                float a = As[ty * 8 + ii][kk];
                acc[ii][0] += a * b.x;
                acc[ii][1] += a * b.y;
                acc[ii][2] += a * b.z;
                acc[ii][3] += a * b.w;
            }
        }
        __syncthreads();
    }

    // ---- epilogue ----
#pragma unroll
    for (int ii = 0; ii < 8; ii++) {
        int row = m0 + ty * 8 + ii;
        if (row >= M) continue;
#pragma unroll
        for (int jj = 0; jj < 4; jj++) {
            int j = n0 + tx * 4 + jj;
            if (j >= HD) continue;
            float v = acc[ii][jj];
            if constexpr (EPI == 1) v += bias[j];
            if constexpr (EPI == 2) v = fmaxf(v + bias[j], 0.f);
            C[row * HD + j] = v;
        }
    }
}

// ---------------- elementwise kernels ----------------
__global__ void gather_k(const float* __restrict__ m, const float* __restrict__ rm,
                         float* __restrict__ sb, float* __restrict__ ab,
                         int lo, int cnt, int total)
{
    int idx = blockIdx.x * blockDim.x + threadIdx.x;
    if (idx >= total) return;
    int a = idx / HD, h = idx - a * HD;
    int t = a / cnt, ci = lo + (a - t * cnt);
    float sv = 0.f, av = 0.f;
    int c1 = 2 * ci + 1;
    if (c1 < NTREE) {
        int g = (t * NTREE + c1) * HD + h;
        sv += m[g]; av += rm[g];
    }
    int c2 = 2 * ci + 2;
    if (c2 < NTREE) {
        int g = (t * NTREE + c2) * HD + h;
        sv += m[g]; av += rm[g];
    }
    sb[idx] = sv; ab[idx] = av;
}

__global__ void mnew_k(const float* __restrict__ xz, const float* __restrict__ xh,
                       const float* __restrict__ sb, const float* __restrict__ zp,
                       const float* __restrict__ hp, float* __restrict__ m,
                       int lo, int cnt, int total)
{
    int idx = blockIdx.x * blockDim.x + threadIdx.x;
    if (idx >= total) return;
    int a = idx / HD, h = idx - a * HD;
    int t = a / cnt, ci = lo + (a - t * cnt);
    int g = (t * NTREE + ci) * HD + h;
    float z  = 1.f / (1.f + expf(-(xz[g] + zp[idx])));
    float th = tanhf(xh[g] + hp[idx]);
    m[g] = (1.f - z) * sb[idx] + z * th;
}

__global__ void rmk_k(const float* __restrict__ xr, const float* __restrict__ rp,
                      const float* __restrict__ m, float* __restrict__ rm,
                      int lo, int cnt, int total)
{
    int idx = blockIdx.x * blockDim.x + threadIdx.x;
    if (idx >= total) return;
    int a = idx / HD, h = idx - a * HD;
    int t = a / cnt, ci = lo + (a - t * cnt);
    int p = (ci - 1) >> 1;
    int gp = (t * NTREE + p) * HD + h;
    int g  = (t * NTREE + ci) * HD + h;
    float r = 1.f / (1.f + expf(-(xr[gp] + rp[idx])));
    rm[g] = r * m[g];
}

// ---------------- launch ----------------
extern "C" void kernel_launch(void* const* d_in, const int* in_sizes, int n_in,
                              void* d_out, int out_size)
{
    const int*   wid = (const int*)  d_in[0];
    const float* emb = (const float*)d_in[1];
    const float* Wz  = (const float*)d_in[2];
    const float* bz  = (const float*)d_in[3];
    const float* Wr  = (const float*)d_in[4];
    const float* Ur  = (const float*)d_in[5];
    const float* bU  = (const float*)d_in[6];
    const float* Wh  = (const float*)d_in[7];
    const float* bh  = (const float*)d_in[8];
    const float* Wg  = (const float*)d_in[9];
    const float* bg  = (const float*)d_in[10];
    float* out = (float*)d_out;

    float *xz, *xh, *xr, *m, *rm, *sb, *ab, *zp, *hp, *rp;
    cudaGetSymbolAddress((void**)&xz, g_xz);
    cudaGetSymbolAddress((void**)&xh, g_xh);
    cudaGetSymbolAddress((void**)&xr, g_xr);
    cudaGetSymbolAddress((void**)&m,  g_m);
    cudaGetSymbolAddress((void**)&rm, g_rm);
    cudaGetSymbolAddress((void**)&sb, g_s);
    cudaGetSymbolAddress((void**)&ab, g_av);
    cudaGetSymbolAddress((void**)&zp, g_zp);
    cudaGetSymbolAddress((void**)&hp, g_hp);
    cudaGetSymbolAddress((void**)&rp, g_rp);

    auto ggrid = [](int M) { return dim3((HD + GBN - 1) / GBN, (M + GBM - 1) / GBM); };

    // Precompute per-node GEMM halves (emb gather fused):
    gemm_k<2, 1><<<ggrid(NNODE), 256>>>(nullptr, Wz, bz, xz, NNODE, HD, 0, 1, wid, emb, nullptr);
    gemm_k<2, 1><<<ggrid(NNODE), 256>>>(nullptr, Wh, bh, xh, NNODE, HD, 0, 1, wid, emb, nullptr);
    gemm_k<2, 1><<<ggrid(NNODE), 256>>>(nullptr, Wr, bU, xr, NNODE, HD, 0, 1, wid, emb, nullptr);

    const int LO[5]  = {31, 15, 7, 3, 1};
    const int CNT[5] = { 1, 16, 8, 4, 2};

    for (int L = 0; L < 5; L++) {
        int lo = LO[L], cnt = CNT[L];
        int Mact = NB * cnt;
        int total = Mact * HD;
        int gb = (total + 255) / 256;

        gather_k<<<gb, 256>>>(m, rm, sb, ab, lo, cnt, total);
        // zp = s @ Wz_bot ; hp = arm @ Wh_bot   (bottom halves = rows 450..899)
        gemm_k<0, 0><<<ggrid(Mact), 256>>>(sb, Wz + HD * HD, nullptr, zp, Mact, HD, 0, 1, nullptr, nullptr, nullptr);
        gemm_k<0, 0><<<ggrid(Mact), 256>>>(ab, Wh + HD * HD, nullptr, hp, Mact, HD, 0, 1, nullptr, nullptr, nullptr);
        mnew_k<<<gb, 256>>>(xz, xh, sb, zp, hp, m, lo, cnt, total);
        if (L < 4) { // level-4 rm is never consumed
            gemm_k<1, 0><<<ggrid(Mact), 256>>>(m, Ur, nullptr, rp, Mact, HD, lo, cnt, nullptr, nullptr, nullptr);
            rmk_k<<<gb, 256>>>(xr, rp, m, rm, lo, cnt, total);
        }
    }

    // Final: out[t] = relu([x_root | m[t,1]+m[t,2]] @ Wg + bg), K = 900
    gemm_k<3, 2><<<ggrid(NB), 256>>>(nullptr, Wg, bg, out, NB, 2 * HD, 0, 1, wid, emb, m);
}

// round 2
// speedup vs baseline: 1.0058x; 1.0058x over previous
#include <cuda_runtime.h>
#include <math.h>

#define HD 450
#define NTREE 32
#define NB 1024
#define NNODE (NB*NTREE)

// ---------------- scratch (static device memory; no allocations) ----------------
__device__ float g_xz[NNODE*HD];   // x@Wz_top + bz  (per node)
__device__ float g_xh[NNODE*HD];   // x@Wh_top + bh
__device__ float g_xr[NNODE*HD];   // x@Wr + bU
__device__ float g_m [NNODE*HD];   // message per upward edge, indexed by child node
__device__ float g_rm[NNODE*HD];   // r*m per upward edge
__device__ float g_s [NB*16*HD];   // level scratch (max 16 active nodes/tree)
__device__ float g_av[NB*16*HD];
__device__ float g_zp[NB*16*HD];
__device__ float g_hp[NB*16*HD];
__device__ float g_rp[NB*16*HD];

constexpr int GBM = 128;
constexpr int GBN = 64;
constexpr int GBK = 16;

// ---------------- generic tiled SGEMM, N fixed = 450 ----------------
// C[M x 450] = Arows[M x K] @ W[K x 450] (+bias) with pluggable A-row source:
//  AMODE 0: dense A (stride 450)
//  AMODE 1: A = g_m with node map: row a -> node (a/cnt)*32 + lo + a%cnt
//  AMODE 2: A = emb[wid[row]]  (precompute gather)
//  AMODE 3: final: row = tree t; k<450 -> emb[wid[t*32]][k]; else m[t,1]+m[t,2]
//  EPI 0: plain store; EPI 1: +bias; EPI 2: relu(acc+bias) (final output)
template<int AMODE, int EPI>
__global__ __launch_bounds__(256) void gemm_k(
    const float* __restrict__ A, const float* __restrict__ W,
    const float* __restrict__ bias, float* __restrict__ C,
    int M, int K, int lo, int cnt,
    const int* __restrict__ wid, const float* __restrict__ emb,
    const float* __restrict__ maux)
{
    __shared__ float As[GBM][GBK];
    __shared__ float Bs[GBK][GBN];

    const int tid = threadIdx.x;
    const int m0 = blockIdx.y * GBM;
    const int n0 = blockIdx.x * GBN;
    const int tx = tid & 15;
    const int ty = tid >> 4;

    float acc[8][4];
#pragma unroll
    for (int i = 0; i < 8; i++)
#pragma unroll
        for (int j = 0; j < 4; j++) acc[i][j] = 0.f;

    for (int k0 = 0; k0 < K; k0 += GBK) {
        // ---- load A tile (128 x 16) as float2, coalesced ----
#pragma unroll
        for (int i = 0; i < 4; i++) {
            int lin = tid + i * 256;           // 0..1023 (float2 index)
            int row = lin >> 3;                // 0..127
            int k2  = lin & 7;
            int k   = k0 + k2 * 2;             // even
            int arow = m0 + row;
            float2 v = make_float2(0.f, 0.f);
            if (arow < M) {
                if constexpr (AMODE == 0) {
                    if (k + 1 < K)      v = *(const float2*)&A[arow * HD + k];
                    else if (k < K)     v.x = A[arow * HD + k];
                } else if constexpr (AMODE == 1) {
                    int tt = arow / cnt;
                    int node = tt * NTREE + lo + (arow - tt * cnt);
                    if (k + 1 < K)      v = *(const float2*)&A[node * HD + k];
                    else if (k < K)     v.x = A[node * HD + k];
                } else if constexpr (AMODE == 2) {
                    int w = wid[arow];
                    if (k + 1 < K)      v = *(const float2*)&emb[w * HD + k];
                    else if (k < K)     v.x = emb[w * HD + k];
                } else { // AMODE == 3
                    if (k < HD) {
                        v = *(const float2*)&emb[wid[arow * NTREE] * HD + k];
                    } else if (k < K) {
                        int kk = k - HD;
                        float2 u1 = *(const float2*)&maux[(arow * NTREE + 1) * HD + kk];
                        float2 u2 = *(const float2*)&maux[(arow * NTREE + 2) * HD + kk];
                        v = make_float2(u1.x + u2.x, u1.y + u2.y);
                    }
                }
            }
            *(float2*)&As[row][k2 * 2] = v;
        }
        // ---- load B tile (16 x 64) ----
#pragma unroll
        for (int i = 0; i < 4; i++) {
            int lin = tid + i * 256;     // 0..1023
            int kk  = lin >> 6;          // 0..15
            int col = lin & 63;
            int k   = k0 + kk;
            int j   = n0 + col;
            Bs[kk][col] = (k < K && j < HD) ? W[k * HD + j] : 0.f;
        }
        __syncthreads();

#pragma unroll
        for (int kk = 0; kk < GBK; kk++) {
            float4 b = *(const float4*)&Bs[kk][tx * 4];
#pragma unroll
            for (int ii = 0; ii < 8; ii++) {
                float a = As[ty * 8 + ii][kk];
                acc[ii][0] += a * b.x;
                acc[ii][1] += a * b.y;
                acc[ii][2] += a * b.z;
                acc[ii][3] += a * b.w;
            }
        }
        __syncthreads();
    }

    // ---- epilogue ----
#pragma unroll
    for (int ii = 0; ii < 8; ii++) {
        int row = m0 + ty * 8 + ii;
        if (row >= M) continue;
#pragma unroll
        for (int jj = 0; jj < 4; jj++) {
            int j = n0 + tx * 4 + jj;
            if (j >= HD) continue;
            float v = acc[ii][jj];
            if constexpr (EPI == 1) v += bias[j];
            if constexpr (EPI == 2) v = fmaxf(v + bias[j], 0.f);
            C[row * HD + j] = v;
        }
    }
}

// ---------------- elementwise kernels ----------------
__global__ void gather_k(const float* __restrict__ m, const float* __restrict__ rm,
                         float* __restrict__ sb, float* __restrict__ ab,
                         int lo, int cnt, int total)
{
    int idx = blockIdx.x * blockDim.x + threadIdx.x;
    if (idx >= total) return;
    int a = idx / HD, h = idx - a * HD;
    int t = a / cnt, ci = lo + (a - t * cnt);
    float sv = 0.f, av = 0.f;
    int c1 = 2 * ci + 1;
    if (c1 < NTREE) {
        int g = (t * NTREE + c1) * HD + h;
        sv += m[g]; av += rm[g];
    }
    int c2 = 2 * ci + 2;
    if (c2 < NTREE) {
        int g = (t * NTREE + c2) * HD + h;
        sv += m[g]; av += rm[g];
    }
    sb[idx] = sv; ab[idx] = av;
}

__global__ void mnew_k(const float* __restrict__ xz, const float* __restrict__ xh,
                       const float* __restrict__ sb, const float* __restrict__ zp,
                       const float* __restrict__ hp, float* __restrict__ m,
                       int lo, int cnt, int total)
{
    int idx = blockIdx.x * blockDim.x + threadIdx.x;
    if (idx >= total) return;
    int a = idx / HD, h = idx - a * HD;
    int t = a / cnt, ci = lo + (a - t * cnt);
    int g = (t * NTREE + ci) * HD + h;
    float z  = 1.f / (1.f + expf(-(xz[g] + zp[idx])));
    float th = tanhf(xh[g] + hp[idx]);
    m[g] = (1.f - z) * sb[idx] + z * th;
}

__global__ void rmk_k(const float* __restrict__ xr, const float* __restrict__ rp,
                      const float* __restrict__ m, float* __restrict__ rm,
                      int lo, int cnt, int total)
{
    int idx = blockIdx.x * blockDim.x + threadIdx.x;
    if (idx >= total) return;
    int a = idx / HD, h = idx - a * HD;
    int t = a / cnt, ci = lo + (a - t * cnt);
    int p = (ci - 1) >> 1;
    int gp = (t * NTREE + p) * HD + h;
    int g  = (t * NTREE + ci) * HD + h;
    float r = 1.f / (1.f + expf(-(xr[gp] + rp[idx])));
    rm[g] = r * m[g];
}

// ---------------- launch ----------------
extern "C" void kernel_launch(void* const* d_in, const int* in_sizes, int n_in,
                              void* d_out, int out_size)
{
    const int*   wid = (const int*)  d_in[0];
    const float* emb = (const float*)d_in[1];
    const float* Wz  = (const float*)d_in[2];
    const float* bz  = (const float*)d_in[3];
    const float* Wr  = (const float*)d_in[4];
    const float* Ur  = (const float*)d_in[5];
    const float* bU  = (const float*)d_in[6];
    const float* Wh  = (const float*)d_in[7];
    const float* bh  = (const float*)d_in[8];
    const float* Wg  = (const float*)d_in[9];
    const float* bg  = (const float*)d_in[10];
    float* out = (float*)d_out;

    float *xz, *xh, *xr, *m, *rm, *sb, *ab, *zp, *hp, *rp;
    cudaGetSymbolAddress((void**)&xz, g_xz);
    cudaGetSymbolAddress((void**)&xh, g_xh);
    cudaGetSymbolAddress((void**)&xr, g_xr);
    cudaGetSymbolAddress((void**)&m,  g_m);
    cudaGetSymbolAddress((void**)&rm, g_rm);
    cudaGetSymbolAddress((void**)&sb, g_s);
    cudaGetSymbolAddress((void**)&ab, g_av);
    cudaGetSymbolAddress((void**)&zp, g_zp);
    cudaGetSymbolAddress((void**)&hp, g_hp);
    cudaGetSymbolAddress((void**)&rp, g_rp);

    auto ggrid = [](int M) { return dim3((HD + GBN - 1) / GBN, (M + GBM - 1) / GBM); };

    // Precompute per-node GEMM halves (emb gather fused):
    gemm_k<2, 1><<<ggrid(NNODE), 256>>>(nullptr, Wz, bz, xz, NNODE, HD, 0, 1, wid, emb, nullptr);
    gemm_k<2, 1><<<ggrid(NNODE), 256>>>(nullptr, Wh, bh, xh, NNODE, HD, 0, 1, wid, emb, nullptr);
    gemm_k<2, 1><<<ggrid(NNODE), 256>>>(nullptr, Wr, bU, xr, NNODE, HD, 0, 1, wid, emb, nullptr);

    const int LO[5]  = {31, 15, 7, 3, 1};
    const int CNT[5] = { 1, 16, 8, 4, 2};

    for (int L = 0; L < 5; L++) {
        int lo = LO[L], cnt = CNT[L];
        int Mact = NB * cnt;
        int total = Mact * HD;
        int gb = (total + 255) / 256;

        gather_k<<<gb, 256>>>(m, rm, sb, ab, lo, cnt, total);
        // zp = s @ Wz_bot ; hp = arm @ Wh_bot   (bottom halves = rows 450..899)
        gemm_k<0, 0><<<ggrid(Mact), 256>>>(sb, Wz + HD * HD, nullptr, zp, Mact, HD, 0, 1, nullptr, nullptr, nullptr);
        gemm_k<0, 0><<<ggrid(Mact), 256>>>(ab, Wh + HD * HD, nullptr, hp, Mact, HD, 0, 1, nullptr, nullptr, nullptr);
        mnew_k<<<gb, 256>>>(xz, xh, sb, zp, hp, m, lo, cnt, total);
        if (L < 4) { // level-4 rm is never consumed
            gemm_k<1, 0><<<ggrid(Mact), 256>>>(m, Ur, nullptr, rp, Mact, HD, lo, cnt, nullptr, nullptr, nullptr);
            rmk_k<<<gb, 256>>>(xr, rp, m, rm, lo, cnt, total);
        }
    }

    // Final: out[t] = relu([x_root | m[t,1]+m[t,2]] @ Wg + bg), K = 900
    gemm_k<3, 2><<<ggrid(NB), 256>>>(nullptr, Wg, bg, out, NB, 2 * HD, 0, 1, wid, emb, m);
}

// round 3
// speedup vs baseline: 2.5765x; 2.5618x over previous
#include <cuda_runtime.h>
#include <math.h>

#define HD 450
#define NTREE 32
#define NB 1024
#define NNODE (NB*NTREE)
#define NV 780

// ---------------- scratch (static device memory) ----------------
__device__ float g_pz [NV*HD];     // emb@Wz_top + bz   per vocab
__device__ float g_ph [NV*HD];     // emb@Wh_top + bh
__device__ float g_pr [NV*HD];     // emb@Wr + bU
__device__ float g_pgt[NV*HD];     // emb@Wg_top + bg
__device__ float g_mlf[NV*HD];     // leaf message per vocab: sig(pz)*tanh(ph)
__device__ float g_rur[NV*HD];     // mlf @ Ur
__device__ float g_m  [NNODE*HD];  // message per upward edge (indexed by child node)
__device__ float g_rm [NNODE*HD];  // r*m
__device__ float g_zp [NB*8*HD];   // level scratch: s@Wz_bot (max 8 active nodes/tree)

constexpr int TM = 64, TN = 64, TK = 16, NTH = 128;
constexpr int APAD = 68;   // padded row stride in smem (floats)

// ---------------- GEMM body ----------------
// C[M x 450] = Arows[M x K] @ W[K x 450] with fused A sources / epilogues.
// AM 0: dense A, stride 450 (vocab / rUr GEMMs)
// AM 1: A[row] = P[child1(node)] + P[child2(node)]  (child-sum; node from lo,cnt)
// AM 2: A[row] = P[node]                            (Ur GEMM)
// EPI 0: C[row*450+j] = acc + (bias?bias[j]:0)
// EPI 2: m-epilogue:  z=sig(pz_g + zp), th=tanh(ph_g + acc), m[g]=(1-z)*s_j+z*th
// EPI 3: rm-epilogue: r=sig(pr[wid[parent]] + acc), rm[g]=r*m[g][j]
// EPI 4: final:       out[t*450+j] = relu(pgt[wid[t*32]][j] + acc)
template<int AM, int EPI>
__global__ __launch_bounds__(NTH) void gemm_k(
    const float* __restrict__ A, const float* __restrict__ W,
    const float* __restrict__ bias, float* __restrict__ C,
    int M, int K, int lo, int cnt,
    const int* __restrict__ wid,
    const float* __restrict__ pz, const float* __restrict__ ph,
    const float* __restrict__ pr,
    const float* __restrict__ zpb, const float* __restrict__ msrc)
{
    __shared__ float As[TK][APAD];   // transposed: As[k][m]
    __shared__ float Bs[TK][APAD];

    const int tid = threadIdx.x;
    const int n0 = blockIdx.x * TN;
    const int m0 = blockIdx.y * TM;
    const int tx = tid & 15;         // 16 col groups * 4
    const int ty = tid >> 4;         // 8 row groups * 8

    float acc[8][4];
#pragma unroll
    for (int i = 0; i < 8; i++)
#pragma unroll
        for (int j = 0; j < 4; j++) acc[i][j] = 0.f;

    for (int k0 = 0; k0 < K; k0 += TK) {
        // ---- A tile: 64 rows x 16 k, float2 along k ----
#pragma unroll
        for (int i = 0; i < 4; i++) {
            int lin = tid + i * NTH;          // 0..511 (float2 slots)
            int row = lin >> 3;               // 0..63
            int k2  = lin & 7;
            int k   = k0 + k2 * 2;
            int arow = m0 + row;
            float2 v = make_float2(0.f, 0.f);
            if (arow < M && k < K) {
                bool pair = (k + 1 < K);
                if constexpr (AM == 0) {
                    if (pair) v = *(const float2*)&A[arow * HD + k];
                    else      v.x = A[arow * HD + k];
                } else if constexpr (AM == 1) {
                    int t  = arow / cnt;
                    int ci = lo + (arow - t * cnt);
                    int c1 = 2 * ci + 1, c2 = 2 * ci + 2;
                    const float* p1 = &A[(t * NTREE + c1) * HD + k];
                    if (pair) {
                        v = *(const float2*)p1;
                        if (c2 < NTREE) {
                            float2 u = *(const float2*)(p1 + HD);
                            v.x += u.x; v.y += u.y;
                        }
                    } else {
                        v.x = p1[0];
                        if (c2 < NTREE) v.x += p1[HD];
                    }
                } else { // AM == 2
                    int t  = arow / cnt;
                    int ci = lo + (arow - t * cnt);
                    const float* p1 = &A[(t * NTREE + ci) * HD + k];
                    if (pair) v = *(const float2*)p1;
                    else      v.x = p1[0];
                }
            }
            As[k2 * 2][row]     = v.x;
            As[k2 * 2 + 1][row] = v.y;
        }
        // ---- B tile: 16 k x 64 cols, float2 along j ----
#pragma unroll
        for (int i = 0; i < 4; i++) {
            int lin = tid + i * NTH;          // 0..511
            int kk  = lin >> 5;               // 0..15
            int col = (lin & 31) * 2;
            int k   = k0 + kk;
            int j   = n0 + col;
            float2 v = make_float2(0.f, 0.f);
            if (k < K) {
                if (j + 1 < HD)      v = *(const float2*)&W[k * HD + j];
                else if (j < HD)     v.x = W[k * HD + j];
            }
            Bs[kk][col]     = v.x;
            Bs[kk][col + 1] = v.y;
        }
        __syncthreads();

#pragma unroll
        for (int kk = 0; kk < TK; kk++) {
            float4 a0 = *(const float4*)&As[kk][ty * 8];
            float4 a1 = *(const float4*)&As[kk][ty * 8 + 4];
            float4 b  = *(const float4*)&Bs[kk][tx * 4];
            float av[8] = {a0.x, a0.y, a0.z, a0.w, a1.x, a1.y, a1.z, a1.w};
#pragma unroll
            for (int ii = 0; ii < 8; ii++) {
                acc[ii][0] += av[ii] * b.x;
                acc[ii][1] += av[ii] * b.y;
                acc[ii][2] += av[ii] * b.z;
                acc[ii][3] += av[ii] * b.w;
            }
        }
        __syncthreads();
    }

    // ---- epilogue ----
#pragma unroll
    for (int ii = 0; ii < 8; ii++) {
        int row = m0 + ty * 8 + ii;
        if (row >= M) continue;
        int t = 0, ci = 0, g = 0;
        if constexpr (EPI == 2 || EPI == 3) {
            t  = row / cnt;
            ci = lo + (row - t * cnt);
            g  = t * NTREE + ci;
        }
#pragma unroll
        for (int jj = 0; jj < 4; jj++) {
            int j = n0 + tx * 4 + jj;
            if (j >= HD) continue;
            float v = acc[ii][jj];
            if constexpr (EPI == 0) {
                if (bias) v += bias[j];
                C[row * HD + j] = v;
            } else if constexpr (EPI == 2) {
                int w = wid[g];
                float z  = 1.f / (1.f + expf(-(pz[w * HD + j] + zpb[row * HD + j])));
                float th = tanhf(ph[w * HD + j] + v);
                int c1 = 2 * ci + 1, c2 = 2 * ci + 2;
                float sj = msrc[(t * NTREE + c1) * HD + j];
                if (c2 < NTREE) sj += msrc[(t * NTREE + c2) * HD + j];
                C[g * HD + j] = (1.f - z) * sj + z * th;
            } else if constexpr (EPI == 3) {
                int p  = (ci - 1) >> 1;
                int wp = wid[t * NTREE + p];
                float r = 1.f / (1.f + expf(-(pr[wp * HD + j] + v)));
                C[g * HD + j] = r * msrc[g * HD + j];
            } else { // EPI == 4  (final; row == tree index)
                int w0 = wid[row * NTREE];
                C[row * HD + j] = fmaxf(pz[w0 * HD + j] + v, 0.f);  // pz slot carries pgt
            }
        }
    }
}

// ---------------- vocab 4-in-1 GEMM (z-dim selects W/bias/out) ----------------
__global__ __launch_bounds__(NTH) void vocab_k(
    const float* __restrict__ emb,
    const float* __restrict__ Wz, const float* __restrict__ bz,
    const float* __restrict__ Wh, const float* __restrict__ bh,
    const float* __restrict__ Wr, const float* __restrict__ bU,
    const float* __restrict__ Wg, const float* __restrict__ bg,
    float* __restrict__ pz, float* __restrict__ ph,
    float* __restrict__ pr, float* __restrict__ pgt)
{
    const float* W; const float* bias; float* C;
    switch (blockIdx.z) {
        case 0:  W = Wz; bias = bz; C = pz;  break;
        case 1:  W = Wh; bias = bh; C = ph;  break;
        case 2:  W = Wr; bias = bU; C = pr;  break;
        default: W = Wg; bias = bg; C = pgt; break;
    }
    __shared__ float As[TK][APAD];
    __shared__ float Bs[TK][APAD];
    const int tid = threadIdx.x;
    const int n0 = blockIdx.x * TN;
    const int m0 = blockIdx.y * TM;
    const int tx = tid & 15;
    const int ty = tid >> 4;
    const int M = NV, K = HD;

    float acc[8][4];
#pragma unroll
    for (int i = 0; i < 8; i++)
#pragma unroll
        for (int j = 0; j < 4; j++) acc[i][j] = 0.f;

    for (int k0 = 0; k0 < K; k0 += TK) {
#pragma unroll
        for (int i = 0; i < 4; i++) {
            int lin = tid + i * NTH;
            int row = lin >> 3;
            int k2  = lin & 7;
            int k   = k0 + k2 * 2;
            int arow = m0 + row;
            float2 v = make_float2(0.f, 0.f);
            if (arow < M && k + 1 < K) v = *(const float2*)&emb[arow * HD + k];
            else if (arow < M && k < K) v.x = emb[arow * HD + k];
            As[k2 * 2][row]     = v.x;
            As[k2 * 2 + 1][row] = v.y;
        }
#pragma unroll
        for (int i = 0; i < 4; i++) {
            int lin = tid + i * NTH;
            int kk  = lin >> 5;
            int col = (lin & 31) * 2;
            int k   = k0 + kk;
            int j   = n0 + col;
            float2 v = make_float2(0.f, 0.f);
            if (k < K) {
                if (j + 1 < HD)  v = *(const float2*)&W[k * HD + j];
                else if (j < HD) v.x = W[k * HD + j];
            }
            Bs[kk][col]     = v.x;
            Bs[kk][col + 1] = v.y;
        }
        __syncthreads();
#pragma unroll
        for (int kk = 0; kk < TK; kk++) {
            float4 a0 = *(const float4*)&As[kk][ty * 8];
            float4 a1 = *(const float4*)&As[kk][ty * 8 + 4];
            float4 b  = *(const float4*)&Bs[kk][tx * 4];
            float av[8] = {a0.x, a0.y, a0.z, a0.w, a1.x, a1.y, a1.z, a1.w};
#pragma unroll
            for (int ii = 0; ii < 8; ii++) {
                acc[ii][0] += av[ii] * b.x;
                acc[ii][1] += av[ii] * b.y;
                acc[ii][2] += av[ii] * b.z;
                acc[ii][3] += av[ii] * b.w;
            }
        }
        __syncthreads();
    }
#pragma unroll
    for (int ii = 0; ii < 8; ii++) {
        int row = m0 + ty * 8 + ii;
        if (row >= M) continue;
#pragma unroll
        for (int jj = 0; jj < 4; jj++) {
            int j = n0 + tx * 4 + jj;
            if (j >= HD) continue;
            C[row * HD + j] = acc[ii][jj] + bias[j];
        }
    }
}

// ---------------- elementwise kernels ----------------
__global__ void mleaf_k(const float* __restrict__ pz, const float* __restrict__ ph,
                        float* __restrict__ mlf)
{
    int idx = blockIdx.x * blockDim.x + threadIdx.x;
    if (idx >= NV * HD) return;
    float z = 1.f / (1.f + expf(-pz[idx]));
    mlf[idx] = z * tanhf(ph[idx]);
}

// leaves: nodes 16..31 of every tree; m & rm are pure vocab gathers
__global__ void leaf_k(const int* __restrict__ wid,
                       const float* __restrict__ mlf, const float* __restrict__ rur,
                       const float* __restrict__ pr,
                       float* __restrict__ m, float* __restrict__ rm)
{
    int idx = blockIdx.x * blockDim.x + threadIdx.x;
    int total = NB * 16 * HD;
    if (idx >= total) return;
    int a = idx / HD, h = idx - a * HD;
    int t = a >> 4;
    int ci = 16 + (a & 15);
    int g = t * NTREE + ci;
    int w = wid[g];
    int p = (ci - 1) >> 1;
    int wp = wid[t * NTREE + p];
    float mv = mlf[w * HD + h];
    m[g * HD + h] = mv;
    float r = 1.f / (1.f + expf(-(pr[wp * HD + h] + rur[w * HD + h])));
    rm[g * HD + h] = r * mv;
}

// ---------------- launch ----------------
extern "C" void kernel_launch(void* const* d_in, const int* in_sizes, int n_in,
                              void* d_out, int out_size)
{
    const int*   wid = (const int*)  d_in[0];
    const float* emb = (const float*)d_in[1];
    const float* Wz  = (const float*)d_in[2];
    const float* bz  = (const float*)d_in[3];
    const float* Wr  = (const float*)d_in[4];
    const float* Ur  = (const float*)d_in[5];
    const float* bU  = (const float*)d_in[6];
    const float* Wh  = (const float*)d_in[7];
    const float* bh  = (const float*)d_in[8];
    const float* Wg  = (const float*)d_in[9];
    const float* bg  = (const float*)d_in[10];
    float* out = (float*)d_out;

    float *pz, *ph, *pr, *pgt, *mlf, *rur, *m, *rm, *zp;
    cudaGetSymbolAddress((void**)&pz,  g_pz);
    cudaGetSymbolAddress((void**)&ph,  g_ph);
    cudaGetSymbolAddress((void**)&pr,  g_pr);
    cudaGetSymbolAddress((void**)&pgt, g_pgt);
    cudaGetSymbolAddress((void**)&mlf, g_mlf);
    cudaGetSymbolAddress((void**)&rur, g_rur);
    cudaGetSymbolAddress((void**)&m,   g_m);
    cudaGetSymbolAddress((void**)&rm,  g_rm);
    cudaGetSymbolAddress((void**)&zp,  g_zp);

    auto grid2 = [](int M) { return dim3((HD + TN - 1) / TN, (M + TM - 1) / TM); };

    // 1) vocab tables: pz, ph, pr, pgt  (M = 780)
    {
        dim3 g((HD + TN - 1) / TN, (NV + TM - 1) / TM, 4);
        vocab_k<<<g, NTH>>>(emb, Wz, bz, Wh, bh, Wr, bU, Wg, bg, pz, ph, pr, pgt);
    }
    // 2) leaf message table + its Ur image
    {
        int tot = NV * HD;
        mleaf_k<<<(tot + 255) / 256, 256>>>(pz, ph, mlf);
        gemm_k<0, 0><<<grid2(NV), NTH>>>(mlf, Ur, nullptr, rur, NV, HD, 0, 1,
                                         nullptr, nullptr, nullptr, nullptr, nullptr, nullptr);
    }
    // 3) all leaves (nodes 16..31): m, rm by gather
    {
        int tot = NB * 16 * HD;
        leaf_k<<<(tot + 255) / 256, 256>>>(wid, mlf, rur, pr, m, rm);
    }

    // 4) interior levels (non-leaf nodes only)
    const int LO[4]  = {15, 7, 3, 1};
    const int CNT[4] = { 1, 8, 4, 2};
    for (int L = 0; L < 4; L++) {
        int lo = LO[L], cnt = CNT[L];
        int Mact = NB * cnt;
        // zp = (m[c1]+m[c2]) @ Wz_bot
        gemm_k<1, 0><<<grid2(Mact), NTH>>>(m, Wz + HD * HD, nullptr, zp, Mact, HD, lo, cnt,
                                           nullptr, nullptr, nullptr, nullptr, nullptr, nullptr);
        // acc_h = (rm[c1]+rm[c2]) @ Wh_bot, fused m-epilogue
        gemm_k<1, 2><<<grid2(Mact), NTH>>>(rm, Wh + HD * HD, nullptr, m, Mact, HD, lo, cnt,
                                           wid, pz, ph, nullptr, zp, m);
        if (L < 3) {
            // acc_r = m[node] @ Ur, fused rm-epilogue
            gemm_k<2, 3><<<grid2(Mact), NTH>>>(m, Ur, nullptr, rm, Mact, HD, lo, cnt,
                                               wid, nullptr, nullptr, pr, nullptr, m);
        }
    }

    // 5) final: out[t] = relu(pgt[wid[t*32]] + (m[1]+m[2]) @ Wg_bot)
    gemm_k<1, 4><<<grid2(NB), NTH>>>(m, Wg + HD * HD, nullptr, out, NB, HD, 0, 1,
                                     wid, pgt, nullptr, nullptr, nullptr, nullptr);
}

// round 5
// speedup vs baseline: 5.1692x; 2.0063x over previous
#include <cuda_runtime.h>
#include <cuda_bf16.h>
#include <math.h>
#include <cstdint>

#define HD 450
#define NTREE 32
#define NB 1024
#define NNODE (NB*NTREE)
#define NV 780

// ---------------- scratch (static device memory) ----------------
__device__ float g_pz [NV*HD];     // emb@Wz_top + bz   per vocab
__device__ float g_ph [NV*HD];     // emb@Wh_top + bh
__device__ float g_pr [NV*HD];     // emb@Wr + bU
__device__ float g_pgt[NV*HD];     // emb@Wg_top + bg
__device__ float g_mlf[NV*HD];     // leaf message per vocab
__device__ float g_rur[NV*HD];     // mlf @ Ur
__device__ float g_m  [NNODE*HD];  // message per upward edge (indexed by child node)
__device__ float g_rm [NNODE*HD];  // r*m
__device__ float g_zp [NB*8*HD];   // s@Wz_bot
__device__ float g_hp [NB*8*HD];   // arm@Wh_bot

// ================= mma.sync helpers (sm_80+ PTX, legal on sm_100) =================
constexpr int BM = 128, BN = 64, BK = 32;
constexpr int ASTR = 40;   // A smem row stride in bf16 (conflict-free ldmatrix)
constexpr int BSTR = 72;   // B smem row stride in bf16

__device__ __forceinline__ void ldm_x4(uint32_t* r, uint32_t addr) {
    asm volatile("ldmatrix.sync.aligned.m8n8.x4.shared.b16 {%0,%1,%2,%3}, [%4];"
                 : "=r"(r[0]), "=r"(r[1]), "=r"(r[2]), "=r"(r[3]) : "r"(addr));
}
__device__ __forceinline__ void ldm_x2t(uint32_t* r, uint32_t addr) {
    asm volatile("ldmatrix.sync.aligned.m8n8.x2.trans.shared.b16 {%0,%1}, [%2];"
                 : "=r"(r[0]), "=r"(r[1]) : "r"(addr));
}
__device__ __forceinline__ void mma_bf16(float* c, const uint32_t* a, const uint32_t* b) {
    asm volatile("mma.sync.aligned.m16n8k16.row.col.f32.bf16.bf16.f32 "
                 "{%0,%1,%2,%3}, {%4,%5,%6,%7}, {%8,%9}, {%0,%1,%2,%3};"
                 : "+f"(c[0]), "+f"(c[1]), "+f"(c[2]), "+f"(c[3])
                 : "r"(a[0]), "r"(a[1]), "r"(a[2]), "r"(a[3]), "r"(b[0]), "r"(b[1]));
}
__device__ __forceinline__ void split2(float2 v, uint32_t& hi, uint32_t& lo) {
    __nv_bfloat162 h = __floats2bfloat162_rn(v.x, v.y);
    __nv_bfloat162 l = __floats2bfloat162_rn(v.x - __bfloat162float(h.x),
                                             v.y - __bfloat162float(h.y));
    hi = *(uint32_t*)&h;
    lo = *(uint32_t*)&l;
}

// ================= GEMM body =================
// C[M x 450] = gatherA[M x 450] @ W[450 x 450] (fp32 via bf16x3 split on tensor pipe)
// AM: 0 dense A; 1 child-sum A[row]=P[c1](+P[c1+1]); 2 node A[row]=P[node]
// EPI: 0 plain; 1 +bias; 3 rm=sig(pr[wp]+acc)*msrc; 4 relu(ptab[w0]+acc)
template<int AM, int EPI>
__device__ __forceinline__ void mma_gemm_body(
    const float* __restrict__ A, const float* __restrict__ W,
    const float* __restrict__ bias, float* __restrict__ C,
    int M, int lo, int lg,
    const int* __restrict__ wid,
    const float* __restrict__ ptab,     // EPI4: pgt
    const float* __restrict__ pr,       // EPI3
    const float* __restrict__ msrc)     // EPI3: m
{
    __shared__ __align__(16) __nv_bfloat16 Ah[BM * ASTR];
    __shared__ __align__(16) __nv_bfloat16 Al[BM * ASTR];
    __shared__ __align__(16) __nv_bfloat16 Bh[BK * BSTR];
    __shared__ __align__(16) __nv_bfloat16 Bl[BK * BSTR];

    const int tid = threadIdx.x;
    const int lane = tid & 31, wrp = tid >> 5;
    const int wm = wrp & 3, wn = wrp >> 2;          // 4 warps M x 2 warps N
    const int n0 = blockIdx.x * BN, m0 = blockIdx.y * BM;

    const uint32_t sAh = (uint32_t)__cvta_generic_to_shared(Ah);
    const uint32_t sAl = (uint32_t)__cvta_generic_to_shared(Al);
    const uint32_t sBh = (uint32_t)__cvta_generic_to_shared(Bh);
    const uint32_t sBl = (uint32_t)__cvta_generic_to_shared(Bl);

    float acc[2][4][4] = {};

    // ldmatrix lane addressing
    const int q = lane >> 3, r8 = lane & 7;
    const int arow_off = (q & 1) * 8 + r8;          // A: row within 16x16 tile
    const int acol_off = (q >> 1) * 8;              // A: col within tile
    const int l16 = lane & 15;
    const int bk_off = (l16 >> 3) * 8 + (l16 & 7);  // B: k-row within 16x8 tile

    for (int k0 = 0; k0 < HD; k0 += BK) {
        // ---- fill A tile: 128 x 32 (hi/lo), 2048 float2 slots ----
#pragma unroll
        for (int i = 0; i < 8; i++) {
            int idx = tid + i * 256;
            int row = idx >> 4;
            int col = (idx & 15) * 2;
            int k = k0 + col;
            int arow = m0 + row;
            float2 v = make_float2(0.f, 0.f);
            if (arow < M && k < HD) {
                if constexpr (AM == 0) {
                    v = *(const float2*)&A[arow * HD + k];
                } else if constexpr (AM == 1) {
                    int t  = arow >> lg;
                    int ci = lo + (arow & ((1 << lg) - 1));
                    int c1 = 2 * ci + 1;
                    const float* p1 = &A[(t * NTREE + c1) * HD + k];
                    v = *(const float2*)p1;
                    if (c1 + 1 < NTREE) {
                        float2 u = *(const float2*)(p1 + HD);
                        v.x += u.x; v.y += u.y;
                    }
                } else { // AM == 2
                    int t  = arow >> lg;
                    int ci = lo + (arow & ((1 << lg) - 1));
                    v = *(const float2*)&A[(t * NTREE + ci) * HD + k];
                }
            }
            uint32_t hp, lp;
            split2(v, hp, lp);
            *(uint32_t*)&Ah[row * ASTR + col] = hp;
            *(uint32_t*)&Al[row * ASTR + col] = lp;
        }
        // ---- fill B tile: 32 k-rows x 64 n (hi/lo), 1024 float2 slots ----
#pragma unroll
        for (int i = 0; i < 4; i++) {
            int idx = tid + i * 256;
            int kk = idx >> 5;
            int col = (idx & 31) * 2;
            int k = k0 + kk, j = n0 + col;
            float2 v = make_float2(0.f, 0.f);
            if (k < HD) {
                if (j + 1 < HD)  v = *(const float2*)&W[k * HD + j];
                else if (j < HD) v.x = W[k * HD + j];
            }
            uint32_t hp, lp;
            split2(v, hp, lp);
            *(uint32_t*)&Bh[kk * BSTR + col] = hp;
            *(uint32_t*)&Bl[kk * BSTR + col] = lp;
        }
        __syncthreads();

        // ---- compute: 2 k-steps of 16 ----
#pragma unroll
        for (int ks = 0; ks < 2; ks++) {
            uint32_t ah[2][4], al[2][4], bh[4][2], bl[4][2];
#pragma unroll
            for (int mf = 0; mf < 2; mf++) {
                int row = wm * 32 + mf * 16 + arow_off;
                int col = ks * 16 + acol_off;
                uint32_t off = (uint32_t)(row * ASTR + col) * 2;
                ldm_x4(ah[mf], sAh + off);
                ldm_x4(al[mf], sAl + off);
            }
#pragma unroll
            for (int nf = 0; nf < 4; nf++) {
                int krow = ks * 16 + bk_off;
                uint32_t off = (uint32_t)(krow * BSTR + wn * 32 + nf * 8) * 2;
                ldm_x2t(bh[nf], sBh + off);
                ldm_x2t(bl[nf], sBl + off);
            }
#pragma unroll
            for (int mf = 0; mf < 2; mf++)
#pragma unroll
                for (int nf = 0; nf < 4; nf++) {
                    mma_bf16(acc[mf][nf], ah[mf], bh[nf]);   // hi*hi
                    mma_bf16(acc[mf][nf], ah[mf], bl[nf]);   // hi*lo
                    mma_bf16(acc[mf][nf], al[mf], bh[nf]);   // lo*hi
                }
        }
        __syncthreads();
    }

    // ---- epilogue: C fragment mapping (m16n8k16) ----
    const int gr = lane >> 2, gc = (lane & 3) * 2;
#pragma unroll
    for (int mf = 0; mf < 2; mf++) {
#pragma unroll
        for (int h = 0; h < 2; h++) {
            int arow = m0 + wm * 32 + mf * 16 + h * 8 + gr;
            if (arow >= M) continue;
            int g = 0, wp = 0, w0 = 0;
            if constexpr (EPI == 3) {
                int t  = arow >> lg;
                int ci = lo + (arow & ((1 << lg) - 1));
                g  = t * NTREE + ci;
                wp = wid[t * NTREE + ((ci - 1) >> 1)];
            } else if constexpr (EPI == 4) {
                w0 = wid[arow * NTREE];
            }
#pragma unroll
            for (int nf = 0; nf < 4; nf++) {
                int j = n0 + wn * 32 + nf * 8 + gc;
                if (j >= HD) continue;                  // HD even, j even -> pair safe
                float vx = acc[mf][nf][h * 2];
                float vy = acc[mf][nf][h * 2 + 1];
                if constexpr (EPI == 0) {
                    *(float2*)&C[arow * HD + j] = make_float2(vx, vy);
                } else if constexpr (EPI == 1) {
                    float2 b = *(const float2*)&bias[j];
                    *(float2*)&C[arow * HD + j] = make_float2(vx + b.x, vy + b.y);
                } else if constexpr (EPI == 3) {
                    float2 pv = *(const float2*)&pr[wp * HD + j];
                    float2 mv = *(const float2*)&msrc[g * HD + j];
                    float rx = 1.f / (1.f + expf(-(pv.x + vx)));
                    float ry = 1.f / (1.f + expf(-(pv.y + vy)));
                    *(float2*)&C[g * HD + j] = make_float2(rx * mv.x, ry * mv.y);
                } else { // EPI == 4
                    float2 pv = *(const float2*)&ptab[w0 * HD + j];
                    *(float2*)&C[arow * HD + j] =
                        make_float2(fmaxf(pv.x + vx, 0.f), fmaxf(pv.y + vy, 0.f));
                }
            }
        }
    }
}

// ================= kernel wrappers =================
__global__ __launch_bounds__(256) void tc_vocab(
    const float* emb,
    const float* Wz, const float* bz, const float* Wh, const float* bh,
    const float* Wr, const float* bU, const float* Wg, const float* bg,
    float* pz, float* ph, float* pr, float* pgt)
{
    const float* W; const float* b; float* C;
    switch (blockIdx.z) {
        case 0:  W = Wz; b = bz; C = pz;  break;
        case 1:  W = Wh; b = bh; C = ph;  break;
        case 2:  W = Wr; b = bU; C = pr;  break;
        default: W = Wg; b = bg; C = pgt; break;
    }
    mma_gemm_body<0, 1>(emb, W, b, C, NV, 0, 0, nullptr, nullptr, nullptr, nullptr);
}

__global__ __launch_bounds__(256) void tc_rur(const float* mlf, const float* Ur, float* rur)
{
    mma_gemm_body<0, 0>(mlf, Ur, nullptr, rur, NV, 0, 0, nullptr, nullptr, nullptr, nullptr);
}

__global__ __launch_bounds__(256) void tc_zh(
    const float* m, const float* rm, const float* Wzb, const float* Whb,
    float* zp, float* hp, int M, int lo, int lg)
{
    if (blockIdx.z == 0)
        mma_gemm_body<1, 0>(m,  Wzb, nullptr, zp, M, lo, lg, nullptr, nullptr, nullptr, nullptr);
    else
        mma_gemm_body<1, 0>(rm, Whb, nullptr, hp, M, lo, lg, nullptr, nullptr, nullptr, nullptr);
}

__global__ __launch_bounds__(256) void tc_ur(
    const float* m, const float* Ur, float* rm, int M, int lo, int lg,
    const int* wid, const float* pr)
{
    mma_gemm_body<2, 3>(m, Ur, nullptr, rm, M, lo, lg, wid, nullptr, pr, m);
}

__global__ __launch_bounds__(256) void tc_fin(
    const float* m, const float* Wgb, float* out, const int* wid, const float* pgt)
{
    mma_gemm_body<1, 4>(m, Wgb, nullptr, out, NB, 0, 0, wid, pgt, nullptr, nullptr);
}

// ================= elementwise =================
__global__ void mleaf_k(const float* __restrict__ pz, const float* __restrict__ ph,
                        float* __restrict__ mlf)
{
    int idx = blockIdx.x * blockDim.x + threadIdx.x;
    if (idx >= NV * (HD / 2)) return;
    int j = idx * 2;
    float2 a = *(const float2*)&pz[j];
    float2 b = *(const float2*)&ph[j];
    float zx = 1.f / (1.f + expf(-a.x)), zy = 1.f / (1.f + expf(-a.y));
    *(float2*)&mlf[j] = make_float2(zx * tanhf(b.x), zy * tanhf(b.y));
}

__global__ void leaf2_k(const int* __restrict__ wid,
                        const float* __restrict__ mlf, const float* __restrict__ rur,
                        const float* __restrict__ pr,
                        float* __restrict__ m, float* __restrict__ rm)
{
    int idx = blockIdx.x * blockDim.x + threadIdx.x;
    const int TOT = NB * 16 * (HD / 2);
    if (idx >= TOT) return;
    int a = idx / (HD / 2);
    int j = (idx - a * (HD / 2)) * 2;
    int t = a >> 4, ci = 16 + (a & 15);
    int g = t * NTREE + ci;
    int w = wid[g];
    int wp = wid[t * NTREE + ((ci - 1) >> 1)];
    float2 mv = *(const float2*)&mlf[w * HD + j];
    float2 ru = *(const float2*)&rur[w * HD + j];
    float2 pv = *(const float2*)&pr[wp * HD + j];
    float rx = 1.f / (1.f + expf(-(pv.x + ru.x)));
    float ry = 1.f / (1.f + expf(-(pv.y + ru.y)));
    *(float2*)&m[g * HD + j]  = mv;
    *(float2*)&rm[g * HD + j] = make_float2(rx * mv.x, ry * mv.y);
}

__global__ void mnew2_k(const int* __restrict__ wid,
                        const float* __restrict__ pz, const float* __restrict__ ph,
                        const float* __restrict__ zp, const float* __restrict__ hp,
                        float* __restrict__ m, int lo, int lg, int total2)
{
    int idx = blockIdx.x * blockDim.x + threadIdx.x;
    if (idx >= total2) return;
    int row = idx / (HD / 2);
    int j = (idx - row * (HD / 2)) * 2;
    int t = row >> lg, ci = lo + (row & ((1 << lg) - 1));
    int g = t * NTREE + ci;
    int w = wid[g];
    float2 zpv = *(const float2*)&zp[row * HD + j];
    float2 hpv = *(const float2*)&hp[row * HD + j];
    float2 pzv = *(const float2*)&pz[w * HD + j];
    float2 phv = *(const float2*)&ph[w * HD + j];
    int c1 = 2 * ci + 1;
    float2 s = *(const float2*)&m[(t * NTREE + c1) * HD + j];
    if (c1 + 1 < NTREE) {
        float2 s2 = *(const float2*)&m[(t * NTREE + c1 + 1) * HD + j];
        s.x += s2.x; s.y += s2.y;
    }
    float zx = 1.f / (1.f + expf(-(pzv.x + zpv.x)));
    float zy = 1.f / (1.f + expf(-(pzv.y + zpv.y)));
    float tx = tanhf(phv.x + hpv.x);
    float ty = tanhf(phv.y + hpv.y);
    *(float2*)&m[g * HD + j] = make_float2((1.f - zx) * s.x + zx * tx,
                                           (1.f - zy) * s.y + zy * ty);
}

// ================= launch =================
extern "C" void kernel_launch(void* const* d_in, const int* in_sizes, int n_in,
                              void* d_out, int out_size)
{
    const int*   wid = (const int*)  d_in[0];
    const float* emb = (const float*)d_in[1];
    const float* Wz  = (const float*)d_in[2];
    const float* bz  = (const float*)d_in[3];
    const float* Wr  = (const float*)d_in[4];
    const float* Ur  = (const float*)d_in[5];
    const float* bU  = (const float*)d_in[6];
    const float* Wh  = (const float*)d_in[7];
    const float* bh  = (const float*)d_in[8];
    const float* Wg  = (const float*)d_in[9];
    const float* bg  = (const float*)d_in[10];
    float* out = (float*)d_out;

    float *pz, *ph, *pr, *pgt, *mlf, *rur, *m, *rm, *zp, *hp;
    cudaGetSymbolAddress((void**)&pz,  g_pz);
    cudaGetSymbolAddress((void**)&ph,  g_ph);
    cudaGetSymbolAddress((void**)&pr,  g_pr);
    cudaGetSymbolAddress((void**)&pgt, g_pgt);
    cudaGetSymbolAddress((void**)&mlf, g_mlf);
    cudaGetSymbolAddress((void**)&rur, g_rur);
    cudaGetSymbolAddress((void**)&m,   g_m);
    cudaGetSymbolAddress((void**)&rm,  g_rm);
    cudaGetSymbolAddress((void**)&zp,  g_zp);
    cudaGetSymbolAddress((void**)&hp,  g_hp);

    const int NX = (HD + BN - 1) / BN;   // 8 n-tiles
    auto yb = [](int M) { return (M + BM - 1) / BM; };

    // 1) vocab tables pz, ph, pr, pgt  (M=780, z selects)
    tc_vocab<<<dim3(NX, yb(NV), 4), 256>>>(emb, Wz, bz, Wh, bh, Wr, bU, Wg, bg,
                                           pz, ph, pr, pgt);
    // 2) leaf message table + its Ur image
    mleaf_k<<<(NV * (HD / 2) + 255) / 256, 256>>>(pz, ph, mlf);
    tc_rur<<<dim3(NX, yb(NV)), 256>>>(mlf, Ur, rur);
    // 3) all leaves (nodes 16..31)
    leaf2_k<<<(NB * 16 * (HD / 2) + 255) / 256, 256>>>(wid, mlf, rur, pr, m, rm);

    // 4) interior levels
    const int LO[4] = {15, 7, 3, 1};
    const int LG[4] = { 0, 3, 2, 1};
    for (int L = 0; L < 4; L++) {
        int lo = LO[L], lg = LG[L];
        int M = NB << lg;
        int total2 = M * (HD / 2);
        tc_zh<<<dim3(NX, yb(M), 2), 256>>>(m, rm, Wz + HD * HD, Wh + HD * HD,
                                           zp, hp, M, lo, lg);
        mnew2_k<<<(total2 + 255) / 256, 256>>>(wid, pz, ph, zp, hp, m, lo, lg, total2);
        if (L < 3)
            tc_ur<<<dim3(NX, yb(M)), 256>>>(m, Ur, rm, M, lo, lg, wid, pr);
    }

    // 5) final: out[t] = relu(pgt[wid[t*32]] + (m[1]+m[2]) @ Wg_bot)
    tc_fin<<<dim3(NX, yb(NB)), 256>>>(m, Wg + HD * HD, out, wid, pgt);
}